// round 10
// baseline (speedup 1.0000x reference)
#include <cuda_runtime.h>
#include <cuda_bf16.h>
#include <stdint.h>

#define D_MODEL 1024
#define NHEADS  16
#define HD      64
#define BATCH   4
#define SEQ     2048
#define BH      64
#define MTOK    8192
#define QSCALE  0.18033688011112042f   // 0.125 * log2(e)
#define LOG2E   1.4426950408889634f

// ---------------- scratch globals (allocation-free) ----------------
__device__ __nv_bfloat16 g_qh[8388608], g_ql[8388608];
__device__ __nv_bfloat16 g_kh[8388608], g_kl[8388608];
__device__ __nv_bfloat16 g_vh[8388608], g_vl[8388608];
__device__ __nv_bfloat16 g_xh[8388608], g_xl[8388608];
__device__ __nv_bfloat16 g_wh[4194304], g_wl[4194304];
__device__ __nv_bfloat16 g_ch[8388608], g_cl[8388608];

// ---------------- helpers ----------------
__device__ __forceinline__ uint32_t su32(const void* p) {
    uint32_t a;
    asm("{ .reg .u64 t; cvta.to.shared.u64 t, %1; cvt.u32.u64 %0, t; }" : "=r"(a) : "l"(p));
    return a;
}
__device__ __forceinline__ void cpa16(uint32_t dst, const void* src) {
    asm volatile("cp.async.cg.shared.global [%0], [%1], 16;" :: "r"(dst), "l"(src));
}
__device__ __forceinline__ void cpa4(uint32_t dst, const void* src) {
    asm volatile("cp.async.ca.shared.global [%0], [%1], 4;" :: "r"(dst), "l"(src));
}
#define CP_COMMIT() asm volatile("cp.async.commit_group;" ::: "memory")
#define CP_WAIT0()  asm volatile("cp.async.wait_group 0;" ::: "memory")
#define CP_WAIT1()  asm volatile("cp.async.wait_group 1;" ::: "memory")

__device__ __forceinline__ void ldsm4(uint32_t* r, uint32_t addr) {
    asm volatile("ldmatrix.sync.aligned.m8n8.x4.shared.b16 {%0,%1,%2,%3}, [%4];"
                 : "=r"(r[0]), "=r"(r[1]), "=r"(r[2]), "=r"(r[3]) : "r"(addr));
}
__device__ __forceinline__ void ldsm4t(uint32_t* r, uint32_t addr) {
    asm volatile("ldmatrix.sync.aligned.m8n8.x4.trans.shared.b16 {%0,%1,%2,%3}, [%4];"
                 : "=r"(r[0]), "=r"(r[1]), "=r"(r[2]), "=r"(r[3]) : "r"(addr));
}
__device__ __forceinline__ void mma_bf16(float* c, const uint32_t* a, const uint32_t* b) {
    asm volatile("mma.sync.aligned.m16n8k16.row.col.f32.bf16.bf16.f32 "
                 "{%0,%1,%2,%3}, {%4,%5,%6,%7}, {%8,%9}, {%0,%1,%2,%3};"
                 : "+f"(c[0]), "+f"(c[1]), "+f"(c[2]), "+f"(c[3])
                 : "r"(a[0]), "r"(a[1]), "r"(a[2]), "r"(a[3]), "r"(b[0]), "r"(b[1]));
}
__device__ __forceinline__ float ex2f(float x) {
    float r; asm("ex2.approx.f32 %0, %1;" : "=f"(r) : "f"(x)); return r;
}
// split pair (v0,v1) -> packed bf16 hi pair + bf16 lo-residual pair
__device__ __forceinline__ void split2(float v0, float v1, uint32_t& hi, uint32_t& lo) {
    uint32_t b0 = __float_as_uint(v0), b1 = __float_as_uint(v1);
    uint32_t h0 = (b0 + 0x7FFFu + ((b0 >> 16) & 1u)) & 0xFFFF0000u;
    uint32_t h1 = (b1 + 0x7FFFu + ((b1 >> 16) & 1u)) & 0xFFFF0000u;
    hi = (h0 >> 16) | h1;
    float l0 = v0 - __uint_as_float(h0);
    float l1 = v1 - __uint_as_float(h1);
    asm("cvt.rn.bf16x2.f32 %0, %1, %2;" : "=r"(lo) : "f"(l1), "f"(l0));
}

// ---------------- prep: fp32 -> bf16 hi/lo ----------------
__global__ void split_x_kernel(const float* __restrict__ src) {
    for (size_t i = (size_t)blockIdx.x * blockDim.x + threadIdx.x; i < (size_t)MTOK * D_MODEL;
         i += (size_t)gridDim.x * blockDim.x) {
        float v = src[i];
        __nv_bfloat16 h = __float2bfloat16(v);
        g_xh[i] = h;
        g_xl[i] = __float2bfloat16(v - __bfloat162float(h));
    }
}
__global__ void split_w_kernel(const float* __restrict__ w0, const float* __restrict__ w1,
                               const float* __restrict__ w2, const float* __restrict__ w3) {
    int idx = blockIdx.y;
    const float* src = (idx == 0) ? w0 : (idx == 1) ? w1 : (idx == 2) ? w2 : w3;
    size_t off = (size_t)idx * 1048576;
    for (size_t i = (size_t)blockIdx.x * blockDim.x + threadIdx.x; i < 1048576;
         i += (size_t)gridDim.x * blockDim.x) {
        float v = src[i];
        __nv_bfloat16 h = __float2bfloat16(v);
        g_wh[off + i] = h;
        g_wl[off + i] = __float2bfloat16(v - __bfloat162float(h));
    }
}

// ---------------- projection GEMM (R8 config): 128m x 128n, split bf16 ----------
// OPROJ=0: QKV merged via blockIdx.z (0:Q scaled, 1:K, 2:V) -> hi/lo scratch
// OPROJ=1: O projection (g_c @ Wo^T + bias) -> fp32 out
#define PST 40960

template<int OPROJ>
__global__ void __launch_bounds__(256, 2)
proj_kernel(const float* __restrict__ bias, float* __restrict__ out)
{
    extern __shared__ char smem[];
    const uint32_t sb = su32(smem);
    const int tid = threadIdx.x;
    const int lane = tid & 31, wid = tid >> 5;
    const int wm = wid >> 2, wn = wid & 3;
    const int g = lane >> 2, tig = lane & 3;
    const int m0 = blockIdx.x * 128, n0 = blockIdx.y * 128;
    const int mode = OPROJ ? 3 : (int)blockIdx.z;

    const __nv_bfloat16* Ah = OPROJ ? g_ch : g_xh;
    const __nv_bfloat16* Al = OPROJ ? g_cl : g_xl;
    const __nv_bfloat16* Bh = g_wh + (size_t)mode * 1048576;
    const __nv_bfloat16* Bl = g_wl + (size_t)mode * 1048576;

    float acc[4][4][4];
#pragma unroll
    for (int i = 0; i < 4; i++)
#pragma unroll
        for (int j = 0; j < 4; j++)
#pragma unroll
            for (int e = 0; e < 4; e++) acc[i][j][e] = 0.0f;

    auto load_stage = [&](int kt, int buf) {
        uint32_t base = sb + buf * PST;
#pragma unroll
        for (int t = 0; t < 8; t++) {
            int vi = tid + t * 256;
            int tile = vi >> 9;
            int row = (vi >> 2) & 127;
            int ch = vi & 3;
            const __nv_bfloat16* src;
            if      (tile == 0) src = Ah + (size_t)(m0 + row) * 1024 + kt + ch * 8;
            else if (tile == 1) src = Al + (size_t)(m0 + row) * 1024 + kt + ch * 8;
            else if (tile == 2) src = Bh + (size_t)(n0 + row) * 1024 + kt + ch * 8;
            else                src = Bl + (size_t)(n0 + row) * 1024 + kt + ch * 8;
            cpa16(base + tile * 10240 + row * 80 + ch * 16, src);
        }
        CP_COMMIT();
    };

    load_stage(0, 0);
    for (int s = 0; s < 32; s++) {
        if (s < 31) { load_stage((s + 1) * 32, (s + 1) & 1); CP_WAIT1(); }
        else CP_WAIT0();
        __syncthreads();
        uint32_t base = sb + (s & 1) * PST;
#pragma unroll
        for (int ks = 0; ks < 2; ks++) {
            uint32_t afh[4][4], afl[4][4];
#pragma unroll
            for (int mf = 0; mf < 4; mf++) {
                uint32_t a = base + (uint32_t)(wm * 64 + mf * 16 + (lane & 15)) * 80
                           + (ks * 16 + (lane >> 4) * 8) * 2;
                ldsm4(afh[mf], a);
                ldsm4(afl[mf], a + 10240);
            }
#pragma unroll
            for (int g2 = 0; g2 < 2; g2++) {
                uint32_t bfh[4], bfl[4];
                uint32_t a = base + 20480
                           + (uint32_t)(wn * 32 + g2 * 16 + (lane & 7) + ((lane >> 4) << 3)) * 80
                           + (ks * 16 + ((lane >> 3) & 1) * 8) * 2;
                ldsm4(bfh, a);
                ldsm4(bfl, a + 10240);
#pragma unroll
                for (int mf = 0; mf < 4; mf++)
#pragma unroll
                    for (int j = 0; j < 2; j++) {
                        float* c = acc[mf][g2 * 2 + j];
                        mma_bf16(c, afh[mf], &bfh[j * 2]);
                        mma_bf16(c, afh[mf], &bfl[j * 2]);
                        mma_bf16(c, afl[mf], &bfh[j * 2]);
                    }
            }
        }
        __syncthreads();
    }

    // epilogue
    const float scale = (mode == 0) ? QSCALE : 1.0f;
    __nv_bfloat16* Oh = (mode == 0) ? g_qh : (mode == 1) ? g_kh : g_vh;
    __nv_bfloat16* Ol = (mode == 0) ? g_ql : (mode == 1) ? g_kl : g_vl;
#pragma unroll
    for (int mf = 0; mf < 4; mf++) {
#pragma unroll
        for (int half = 0; half < 2; half++) {
            int m = m0 + wm * 64 + mf * 16 + g + half * 8;
#pragma unroll
            for (int nf = 0; nf < 4; nf++) {
                int n = n0 + wn * 32 + nf * 8 + 2 * tig;
                float v0 = acc[mf][nf][half * 2] * scale;
                float v1 = acc[mf][nf][half * 2 + 1] * scale;
                if (OPROJ) {
                    float2 o = make_float2(v0 + bias[n], v1 + bias[n + 1]);
                    *(float2*)(out + (size_t)m * 1024 + n) = o;
                } else {
                    int b = m >> 11, ss = m & 2047;
                    int h = n >> 6, d = n & 63;
                    size_t addr = (((size_t)(b * 16 + h) * 2048) + ss) * 64 + d;
                    uint32_t hi, lo;
                    split2(v0, v1, hi, lo);
                    *(uint32_t*)(Oh + addr) = hi;
                    *(uint32_t*)(Ol + addr) = lo;
                }
            }
        }
    }
}

// ---------------- attention: split-K dual warp-groups, de-phased streams ---------
// CTA 256 thr = 2 groups x 4 warps. Q-tile 64 rows (warp owns 16). Group g covers
// k in [g*1024, (g+1)*1024) as 8 tiles of 128 rows; single-buffered KV per group;
// NO cross-group barriers in mainloop (bar.sync grp-scoped). Partial O/lsum merged
// by plain add at the end (no max tracking -> sums compose).
// SMEM: QH 0 (9216), QL 9216; KV group g at 18432+g*73728 (KH,KL,VH,VL x 18432);
// merge staging reuses group1 KV area; bias 2x768B at 165888. Total 167424 -> 1 CTA/SM.
#define AT_TS   18432
#define AT_QH   0
#define AT_QL   9216
#define AT_KV   18432
#define AT_KVG  73728
#define AT_SO   92160
#define AT_SL   109568
#define AT_SB   165888
#define AT_SMEM 167424

__global__ void __launch_bounds__(256, 1)
attn_kernel(const float* __restrict__ bias_table)
{
    extern __shared__ char smem[];
    const uint32_t sb = su32(smem);
    const int tid = threadIdx.x;
    const int lane = tid & 31, w = tid >> 5;
    const int g = lane >> 2, tig = lane & 3;
    const int grp = w >> 2;          // warp-group 0/1
    const int wg = w & 3;            // warp within group
    const int gtid = tid & 127;
    const int bh = blockIdx.y;
    const int b = bh >> 4, h = bh & 15;
    const int q0 = blockIdx.x * 64;
    const int kbase = grp * 1024;

    auto barg = [&]() {   // group-scoped barrier
        asm volatile("bar.sync %0, 128;" :: "r"(grp + 1) : "memory");
    };

    auto issue_kv = [&](int k0) {
        uint32_t base = sb + AT_KV + grp * AT_KVG;
#pragma unroll
        for (int u = 0; u < 32; u++) {
            int vi = gtid + u * 128;
            int tile = vi >> 10;          // 0 KH,1 KL,2 VH,3 VL
            int row = (vi >> 3) & 127;
            int ch = vi & 7;
            const __nv_bfloat16* src;
            if      (tile == 0) src = g_kh + ((size_t)bh * 2048 + k0 + row) * 64 + ch * 8;
            else if (tile == 1) src = g_kl + ((size_t)bh * 2048 + k0 + row) * 64 + ch * 8;
            else if (tile == 2) src = g_vh + ((size_t)bh * 2048 + k0 + row) * 64 + ch * 8;
            else                src = g_vl + ((size_t)bh * 2048 + k0 + row) * 64 + ch * 8;
            cpa16(base + tile * AT_TS + row * 144 + ch * 16, src);
        }
        // bias window: 191 values, sbias[i] <-> (q-q0)-(k-k0) = i-127
        uint32_t bdst = sb + AT_SB + grp * 768;
        cpa4(bdst + gtid * 4, bias_table + (size_t)(q0 - k0 + 1920 + gtid) * 16 + h);
        if (gtid < 63)
            cpa4(bdst + (128 + gtid) * 4,
                 bias_table + (size_t)(q0 - k0 + 2048 + gtid) * 16 + h);
    };

    // prologue: Q (all threads) + first KV (per group), one wait
#pragma unroll
    for (int t2 = 0; t2 < 4; t2++) {
        int vi = tid + t2 * 256;          // 0..1023
        int half = vi >> 9;
        int row = (vi >> 3) & 63;
        int ch = vi & 7;
        const __nv_bfloat16* src = (half ? g_ql : g_qh)
            + ((size_t)bh * 2048 + q0 + row) * 64 + ch * 8;
        cpa16(sb + (half ? AT_QL : AT_QH) + row * 144 + ch * 16, src);
    }
    issue_kv(kbase);
    CP_COMMIT();
    CP_WAIT0();
    __syncthreads();

    float oacc[8][4];
#pragma unroll
    for (int i = 0; i < 8; i++)
#pragma unroll
        for (int e = 0; e < 4; e++) oacc[i][e] = 0.0f;
    float lsumA = 0.0f, lsumB = 0.0f;

    const int d0 = wg * 16 + g - 2 * tig + 127;
    const uint32_t kvb = sb + AT_KV + grp * AT_KVG;
    const float* sbias = (const float*)(smem + AT_SB + grp * 768);

    for (int t = 0; t < 8; t++) {
#pragma unroll
        for (int half = 0; half < 2; half++) {
            // ---- S(half) = Q @ K[half]^T (log2-scaled), 64 cols ----
            float sacc[8][4];
#pragma unroll
            for (int i = 0; i < 8; i++)
#pragma unroll
                for (int e = 0; e < 4; e++) sacc[i][e] = 0.0f;
#pragma unroll
            for (int ks = 0; ks < 4; ks++) {
                uint32_t qfh[4], qfl[4];
                {
                    uint32_t a = sb + AT_QH + (uint32_t)(wg * 16 + (lane & 15)) * 144
                               + (ks * 16 + (lane >> 4) * 8) * 2;
                    ldsm4(qfh, a);
                    ldsm4(qfl, a + (AT_QL - AT_QH));
                }
                uint32_t kfh[4][4], kfl[4][4];
#pragma unroll
                for (int g2 = 0; g2 < 4; g2++) {
                    uint32_t a = kvb
                        + (uint32_t)(half * 64 + g2 * 16 + (lane & 7) + ((lane >> 4) << 3)) * 144
                        + (ks * 16 + ((lane >> 3) & 1) * 8) * 2;
                    ldsm4(kfh[g2], a);
                    ldsm4(kfl[g2], a + AT_TS);
                }
#pragma unroll
                for (int nf2 = 0; nf2 < 8; nf2++) {
                    float* c = sacc[nf2];
                    const uint32_t* bhp = &kfh[nf2 >> 1][(nf2 & 1) * 2];
                    const uint32_t* blp = &kfl[nf2 >> 1][(nf2 & 1) * 2];
                    mma_bf16(c, qfh, bhp);
                    mma_bf16(c, qfh, blp);
                    mma_bf16(c, qfl, bhp);
                }
            }

            // ---- P = 2^(S + bias*log2e): C-frag -> A-frag in registers ----
            uint32_t pfh[4][4], pfl[4][4];
#pragma unroll
            for (int ks2 = 0; ks2 < 4; ks2++) {
#pragma unroll
                for (int j = 0; j < 2; j++) {
                    int nf2 = 2 * ks2 + j;
                    float* c = sacc[nf2];
                    int idx = d0 - (half * 8 + nf2) * 8;
                    float p0 = ex2f(fmaf(sbias[idx],     LOG2E, c[0]));
                    float p1 = ex2f(fmaf(sbias[idx - 1], LOG2E, c[1]));
                    float p2 = ex2f(fmaf(sbias[idx + 8], LOG2E, c[2]));
                    float p3 = ex2f(fmaf(sbias[idx + 7], LOG2E, c[3]));
                    lsumA += p0 + p1;
                    lsumB += p2 + p3;
                    split2(p0, p1, pfh[ks2][j * 2 + 0], pfl[ks2][j * 2 + 0]);
                    split2(p2, p3, pfh[ks2][j * 2 + 1], pfl[ks2][j * 2 + 1]);
                }
            }

            // ---- O += P(half) @ V[half] ----
            const uint32_t vb = kvb + 2 * AT_TS;
#pragma unroll
            for (int ks2 = 0; ks2 < 4; ks2++) {
                uint32_t vfh[4][4], vfl[4][4];
#pragma unroll
                for (int dblk = 0; dblk < 4; dblk++) {
                    uint32_t a = vb
                        + (uint32_t)(half * 64 + ks2 * 16 + (lane & 7) + ((lane >> 3) & 1) * 8) * 144
                        + (dblk * 16 + ((lane >> 4) << 3)) * 2;
                    ldsm4t(vfh[dblk], a);
                    ldsm4t(vfl[dblk], a + AT_TS);
                }
#pragma unroll
                for (int dblk = 0; dblk < 4; dblk++)
#pragma unroll
                    for (int sub = 0; sub < 2; sub++) {
                        float* o = oacc[dblk * 2 + sub];
                        mma_bf16(o, pfh[ks2], &vfh[dblk][sub * 2]);
                        mma_bf16(o, pfh[ks2], &vfl[dblk][sub * 2]);
                        mma_bf16(o, pfl[ks2], &vfh[dblk][sub * 2]);
                    }
            }
        }
        if (t < 7) {
            barg();                        // group done reading buffer
            issue_kv(kbase + (t + 1) * 128);
            CP_COMMIT();
            CP_WAIT0();
            barg();                        // loads visible to group
        }
    }

    // ---- merge partials (group1 -> smem, group0 adds) ----
    lsumA += __shfl_xor_sync(0xffffffffu, lsumA, 1);
    lsumA += __shfl_xor_sync(0xffffffffu, lsumA, 2);
    lsumB += __shfl_xor_sync(0xffffffffu, lsumB, 1);
    lsumB += __shfl_xor_sync(0xffffffffu, lsumB, 2);

    float* so = (float*)(smem + AT_SO);    // [64][68] fp32
    float* sl = (float*)(smem + AT_SL);    // [64] fp32
    const int rbase = wg * 16 + g;

    if (grp == 1) {
#pragma unroll
        for (int nfd = 0; nfd < 8; nfd++) {
            int d = nfd * 8 + 2 * tig;
            so[rbase * 68 + d]           = oacc[nfd][0];
            so[rbase * 68 + d + 1]       = oacc[nfd][1];
            so[(rbase + 8) * 68 + d]     = oacc[nfd][2];
            so[(rbase + 8) * 68 + d + 1] = oacc[nfd][3];
        }
        if (tig == 0) { sl[rbase] = lsumA; sl[rbase + 8] = lsumB; }
    }
    __syncthreads();

    if (grp == 0) {
        const float inv0 = 1.0f / (lsumA + sl[rbase]);
        const float inv1 = 1.0f / (lsumB + sl[rbase + 8]);
        const int row0 = q0 + rbase;
        const size_t base0 = (size_t)(b * 2048 + row0) * 1024 + h * 64;
        const size_t base1 = (size_t)(b * 2048 + row0 + 8) * 1024 + h * 64;
#pragma unroll
        for (int nfd = 0; nfd < 8; nfd++) {
            int d = nfd * 8 + 2 * tig;
            float v0 = (oacc[nfd][0] + so[rbase * 68 + d])           * inv0;
            float v1 = (oacc[nfd][1] + so[rbase * 68 + d + 1])       * inv0;
            float v2 = (oacc[nfd][2] + so[(rbase + 8) * 68 + d])     * inv1;
            float v3 = (oacc[nfd][3] + so[(rbase + 8) * 68 + d + 1]) * inv1;
            uint32_t hi, lo;
            split2(v0, v1, hi, lo);
            *(uint32_t*)(g_ch + base0 + d) = hi;
            *(uint32_t*)(g_cl + base0 + d) = lo;
            split2(v2, v3, hi, lo);
            *(uint32_t*)(g_ch + base1 + d) = hi;
            *(uint32_t*)(g_cl + base1 + d) = lo;
        }
    }
}

// ---------------- launch ----------------
extern "C" void kernel_launch(void* const* d_in, const int* in_sizes, int n_in,
                              void* d_out, int out_size)
{
    const float* x  = (const float*)d_in[0];
    const float* Wq = (const float*)d_in[1];
    const float* Wk = (const float*)d_in[2];
    const float* Wv = (const float*)d_in[3];
    const float* Wo = (const float*)d_in[4];
    const float* bo = (const float*)d_in[5];
    const float* bt = (const float*)d_in[6];
    float* out = (float*)d_out;

    cudaFuncSetAttribute(proj_kernel<0>, cudaFuncAttributeMaxDynamicSharedMemorySize, 2 * PST);
    cudaFuncSetAttribute(proj_kernel<1>, cudaFuncAttributeMaxDynamicSharedMemorySize, 2 * PST);
    cudaFuncSetAttribute(attn_kernel,    cudaFuncAttributeMaxDynamicSharedMemorySize, AT_SMEM);

    split_x_kernel<<<2048, 256>>>(x);
    split_w_kernel<<<dim3(256, 4), 256>>>(Wq, Wk, Wv, Wo);

    proj_kernel<0><<<dim3(64, 8, 3), 256, 2 * PST>>>(nullptr, nullptr);

    attn_kernel<<<dim3(32, 64), 256, AT_SMEM>>>(bt);

    proj_kernel<1><<<dim3(64, 8), 256, 2 * PST>>>(bo, out);
}

// round 11
// speedup vs baseline: 1.0850x; 1.0850x over previous
#include <cuda_runtime.h>
#include <cuda_bf16.h>
#include <stdint.h>

#define D_MODEL 1024
#define NHEADS  16
#define HD      64
#define BATCH   4
#define SEQ     2048
#define BH      64
#define MTOK    8192
#define QSCALE  0.18033688011112042f   // 0.125 * log2(e)
#define LOG2E   1.4426950408889634f

// ---------------- scratch globals (allocation-free) ----------------
__device__ __nv_bfloat16 g_qh[8388608], g_ql[8388608];
__device__ __nv_bfloat16 g_kh[8388608], g_kl[8388608];
__device__ __nv_bfloat16 g_vh[8388608], g_vl[8388608];
__device__ __nv_bfloat16 g_xh[8388608], g_xl[8388608];
__device__ __nv_bfloat16 g_wh[4194304], g_wl[4194304];
__device__ __nv_bfloat16 g_ch[8388608], g_cl[8388608];

// ---------------- helpers ----------------
__device__ __forceinline__ uint32_t su32(const void* p) {
    uint32_t a;
    asm("{ .reg .u64 t; cvta.to.shared.u64 t, %1; cvt.u32.u64 %0, t; }" : "=r"(a) : "l"(p));
    return a;
}
__device__ __forceinline__ void cpa16(uint32_t dst, const void* src) {
    asm volatile("cp.async.cg.shared.global [%0], [%1], 16;" :: "r"(dst), "l"(src));
}
__device__ __forceinline__ void cpa4(uint32_t dst, const void* src) {
    asm volatile("cp.async.ca.shared.global [%0], [%1], 4;" :: "r"(dst), "l"(src));
}
#define CP_COMMIT() asm volatile("cp.async.commit_group;" ::: "memory")
#define CP_WAIT0()  asm volatile("cp.async.wait_group 0;" ::: "memory")
#define CP_WAIT1()  asm volatile("cp.async.wait_group 1;" ::: "memory")

__device__ __forceinline__ void ldsm4(uint32_t* r, uint32_t addr) {
    asm volatile("ldmatrix.sync.aligned.m8n8.x4.shared.b16 {%0,%1,%2,%3}, [%4];"
                 : "=r"(r[0]), "=r"(r[1]), "=r"(r[2]), "=r"(r[3]) : "r"(addr));
}
__device__ __forceinline__ void ldsm4t(uint32_t* r, uint32_t addr) {
    asm volatile("ldmatrix.sync.aligned.m8n8.x4.trans.shared.b16 {%0,%1,%2,%3}, [%4];"
                 : "=r"(r[0]), "=r"(r[1]), "=r"(r[2]), "=r"(r[3]) : "r"(addr));
}
__device__ __forceinline__ void mma_bf16(float* c, const uint32_t* a, const uint32_t* b) {
    asm volatile("mma.sync.aligned.m16n8k16.row.col.f32.bf16.bf16.f32 "
                 "{%0,%1,%2,%3}, {%4,%5,%6,%7}, {%8,%9}, {%0,%1,%2,%3};"
                 : "+f"(c[0]), "+f"(c[1]), "+f"(c[2]), "+f"(c[3])
                 : "r"(a[0]), "r"(a[1]), "r"(a[2]), "r"(a[3]), "r"(b[0]), "r"(b[1]));
}
__device__ __forceinline__ float ex2f(float x) {
    float r; asm("ex2.approx.f32 %0, %1;" : "=f"(r) : "f"(x)); return r;
}
// split pair (v0,v1) -> packed bf16 hi pair + bf16 lo-residual pair
__device__ __forceinline__ void split2(float v0, float v1, uint32_t& hi, uint32_t& lo) {
    uint32_t b0 = __float_as_uint(v0), b1 = __float_as_uint(v1);
    uint32_t h0 = (b0 + 0x7FFFu + ((b0 >> 16) & 1u)) & 0xFFFF0000u;
    uint32_t h1 = (b1 + 0x7FFFu + ((b1 >> 16) & 1u)) & 0xFFFF0000u;
    hi = (h0 >> 16) | h1;
    float l0 = v0 - __uint_as_float(h0);
    float l1 = v1 - __uint_as_float(h1);
    asm("cvt.rn.bf16x2.f32 %0, %1, %2;" : "=r"(lo) : "f"(l1), "f"(l0));
}

// ---------------- prep: fp32 -> bf16 hi/lo ----------------
__global__ void split_x_kernel(const float* __restrict__ src) {
    for (size_t i = (size_t)blockIdx.x * blockDim.x + threadIdx.x; i < (size_t)MTOK * D_MODEL;
         i += (size_t)gridDim.x * blockDim.x) {
        float v = src[i];
        __nv_bfloat16 h = __float2bfloat16(v);
        g_xh[i] = h;
        g_xl[i] = __float2bfloat16(v - __bfloat162float(h));
    }
}
__global__ void split_w_kernel(const float* __restrict__ w0, const float* __restrict__ w1,
                               const float* __restrict__ w2, const float* __restrict__ w3) {
    int idx = blockIdx.y;
    const float* src = (idx == 0) ? w0 : (idx == 1) ? w1 : (idx == 2) ? w2 : w3;
    size_t off = (size_t)idx * 1048576;
    for (size_t i = (size_t)blockIdx.x * blockDim.x + threadIdx.x; i < 1048576;
         i += (size_t)gridDim.x * blockDim.x) {
        float v = src[i];
        __nv_bfloat16 h = __float2bfloat16(v);
        g_wh[off + i] = h;
        g_wl[off + i] = __float2bfloat16(v - __bfloat162float(h));
    }
}

// ---------------- projection GEMM (R8 config): 128m x 128n, split bf16 ----------
#define PST 40960

template<int OPROJ>
__global__ void __launch_bounds__(256, 2)
proj_kernel(const float* __restrict__ bias, float* __restrict__ out)
{
    extern __shared__ char smem[];
    const uint32_t sb = su32(smem);
    const int tid = threadIdx.x;
    const int lane = tid & 31, wid = tid >> 5;
    const int wm = wid >> 2, wn = wid & 3;
    const int g = lane >> 2, tig = lane & 3;
    const int m0 = blockIdx.x * 128, n0 = blockIdx.y * 128;
    const int mode = OPROJ ? 3 : (int)blockIdx.z;

    const __nv_bfloat16* Ah = OPROJ ? g_ch : g_xh;
    const __nv_bfloat16* Al = OPROJ ? g_cl : g_xl;
    const __nv_bfloat16* Bh = g_wh + (size_t)mode * 1048576;
    const __nv_bfloat16* Bl = g_wl + (size_t)mode * 1048576;

    float acc[4][4][4];
#pragma unroll
    for (int i = 0; i < 4; i++)
#pragma unroll
        for (int j = 0; j < 4; j++)
#pragma unroll
            for (int e = 0; e < 4; e++) acc[i][j][e] = 0.0f;

    auto load_stage = [&](int kt, int buf) {
        uint32_t base = sb + buf * PST;
#pragma unroll
        for (int t = 0; t < 8; t++) {
            int vi = tid + t * 256;
            int tile = vi >> 9;
            int row = (vi >> 2) & 127;
            int ch = vi & 3;
            const __nv_bfloat16* src;
            if      (tile == 0) src = Ah + (size_t)(m0 + row) * 1024 + kt + ch * 8;
            else if (tile == 1) src = Al + (size_t)(m0 + row) * 1024 + kt + ch * 8;
            else if (tile == 2) src = Bh + (size_t)(n0 + row) * 1024 + kt + ch * 8;
            else                src = Bl + (size_t)(n0 + row) * 1024 + kt + ch * 8;
            cpa16(base + tile * 10240 + row * 80 + ch * 16, src);
        }
        CP_COMMIT();
    };

    load_stage(0, 0);
    for (int s = 0; s < 32; s++) {
        if (s < 31) { load_stage((s + 1) * 32, (s + 1) & 1); CP_WAIT1(); }
        else CP_WAIT0();
        __syncthreads();
        uint32_t base = sb + (s & 1) * PST;
#pragma unroll
        for (int ks = 0; ks < 2; ks++) {
            uint32_t afh[4][4], afl[4][4];
#pragma unroll
            for (int mf = 0; mf < 4; mf++) {
                uint32_t a = base + (uint32_t)(wm * 64 + mf * 16 + (lane & 15)) * 80
                           + (ks * 16 + (lane >> 4) * 8) * 2;
                ldsm4(afh[mf], a);
                ldsm4(afl[mf], a + 10240);
            }
#pragma unroll
            for (int g2 = 0; g2 < 2; g2++) {
                uint32_t bfh[4], bfl[4];
                uint32_t a = base + 20480
                           + (uint32_t)(wn * 32 + g2 * 16 + (lane & 7) + ((lane >> 4) << 3)) * 80
                           + (ks * 16 + ((lane >> 3) & 1) * 8) * 2;
                ldsm4(bfh, a);
                ldsm4(bfl, a + 10240);
#pragma unroll
                for (int mf = 0; mf < 4; mf++)
#pragma unroll
                    for (int j = 0; j < 2; j++) {
                        float* c = acc[mf][g2 * 2 + j];
                        mma_bf16(c, afh[mf], &bfh[j * 2]);
                        mma_bf16(c, afh[mf], &bfl[j * 2]);
                        mma_bf16(c, afl[mf], &bfh[j * 2]);
                    }
            }
        }
        __syncthreads();
    }

    // epilogue
    const float scale = (mode == 0) ? QSCALE : 1.0f;
    __nv_bfloat16* Oh = (mode == 0) ? g_qh : (mode == 1) ? g_kh : g_vh;
    __nv_bfloat16* Ol = (mode == 0) ? g_ql : (mode == 1) ? g_kl : g_vl;
#pragma unroll
    for (int mf = 0; mf < 4; mf++) {
#pragma unroll
        for (int half = 0; half < 2; half++) {
            int m = m0 + wm * 64 + mf * 16 + g + half * 8;
#pragma unroll
            for (int nf = 0; nf < 4; nf++) {
                int n = n0 + wn * 32 + nf * 8 + 2 * tig;
                float v0 = acc[mf][nf][half * 2] * scale;
                float v1 = acc[mf][nf][half * 2 + 1] * scale;
                if (OPROJ) {
                    float2 o = make_float2(v0 + bias[n], v1 + bias[n + 1]);
                    *(float2*)(out + (size_t)m * 1024 + n) = o;
                } else {
                    int b = m >> 11, ss = m & 2047;
                    int h = n >> 6, d = n & 63;
                    size_t addr = (((size_t)(b * 16 + h) * 2048) + ss) * 64 + d;
                    uint32_t hi, lo;
                    split2(v0, v1, hi, lo);
                    *(uint32_t*)(Oh + addr) = hi;
                    *(uint32_t*)(Ol + addr) = lo;
                }
            }
        }
    }
}

// ---------------- attention: pipelined softmax (S0 | S1+sm0 | PV0+sm1 | PV1) -------
// 8 warps x 16 q-rows, 256 thr, 1 CTA/SM. Double-buffered 128-row KV tiles.
// SMEM: QH 0, QL 18432; KV stages at 36864 + s*73728; bias at 184320 + s*1024.
#define AT_TS  18432
#define AT_QH  0
#define AT_QL  18432
#define AT_KV  36864
#define AT_KVS 73728
#define AT_SB  184320
#define AT_SMEM 186368

__global__ void __launch_bounds__(256, 1)
attn_kernel(const float* __restrict__ bias_table)
{
    extern __shared__ char smem[];
    const uint32_t sb = su32(smem);
    const int tid = threadIdx.x;
    const int lane = tid & 31, w = tid >> 5;
    const int g = lane >> 2, tig = lane & 3;
    const int bh = blockIdx.y;
    const int b = bh >> 4, h = bh & 15;
    const int q0 = blockIdx.x * 128;

    // Q tiles hi/lo
#pragma unroll
    for (int t2 = 0; t2 < 8; t2++) {
        int vi = tid + t2 * 256;
        int half = vi >> 10;
        int row = (vi >> 3) & 127;
        int ch = vi & 7;
        const __nv_bfloat16* src = (half ? g_ql : g_qh)
            + ((size_t)bh * 2048 + q0 + row) * 64 + ch * 8;
        cpa16(sb + (half ? AT_QL : AT_QH) + row * 144 + ch * 16, src);
    }

    auto issue_kv = [&](int buf, int k0) {
        uint32_t base = sb + AT_KV + buf * AT_KVS;
#pragma unroll
        for (int u = 0; u < 16; u++) {
            int vi = tid + u * 256;
            int tile = vi >> 10;          // 0 KH,1 KL,2 VH,3 VL
            int row = (vi >> 3) & 127;
            int ch = vi & 7;
            const __nv_bfloat16* src;
            if      (tile == 0) src = g_kh + ((size_t)bh * 2048 + k0 + row) * 64 + ch * 8;
            else if (tile == 1) src = g_kl + ((size_t)bh * 2048 + k0 + row) * 64 + ch * 8;
            else if (tile == 2) src = g_vh + ((size_t)bh * 2048 + k0 + row) * 64 + ch * 8;
            else                src = g_vl + ((size_t)bh * 2048 + k0 + row) * 64 + ch * 8;
            cpa16(base + tile * AT_TS + row * 144 + ch * 16, src);
        }
        if (tid < 255)
            cpa4(sb + AT_SB + buf * 1024 + tid * 4,
                 bias_table + (size_t)(q0 - k0 + 1920 + tid) * 16 + h);
    };

    issue_kv(0, 0);
    CP_COMMIT();   // group: Q + KV0

    float oacc[8][4];
#pragma unroll
    for (int i = 0; i < 8; i++)
#pragma unroll
        for (int e = 0; e < 4; e++) oacc[i][e] = 0.0f;
    float lsumA = 0.0f, lsumB = 0.0f;

    const int d0 = w * 16 + g - 2 * tig + 127;

    for (int t = 0; t < 16; t++) {
        if (t < 15) { issue_kv((t + 1) & 1, (t + 1) * 128); CP_COMMIT(); CP_WAIT1(); }
        else CP_WAIT0();
        __syncthreads();

        const uint32_t kvb = sb + AT_KV + (t & 1) * AT_KVS;
        const float* sbias = (const float*)(smem + AT_SB + (t & 1) * 1024);

        float sacc0[8][4], sacc1[8][4];
#pragma unroll
        for (int i = 0; i < 8; i++)
#pragma unroll
            for (int e = 0; e < 4; e++) { sacc0[i][e] = 0.0f; sacc1[i][e] = 0.0f; }

        // ---- Stage A: S(0) = Q @ K[0:64]^T ----
#pragma unroll
        for (int ks = 0; ks < 4; ks++) {
            uint32_t qfh[4], qfl[4];
            {
                uint32_t a = sb + AT_QH + (uint32_t)(w * 16 + (lane & 15)) * 144
                           + (ks * 16 + (lane >> 4) * 8) * 2;
                ldsm4(qfh, a);
                ldsm4(qfl, a + AT_TS);
            }
            uint32_t kfh[4][4], kfl[4][4];
#pragma unroll
            for (int g2 = 0; g2 < 4; g2++) {
                uint32_t a = kvb
                    + (uint32_t)(g2 * 16 + (lane & 7) + ((lane >> 4) << 3)) * 144
                    + (ks * 16 + ((lane >> 3) & 1) * 8) * 2;
                ldsm4(kfh[g2], a);
                ldsm4(kfl[g2], a + AT_TS);
            }
#pragma unroll
            for (int nf2 = 0; nf2 < 8; nf2++) {
                float* c = sacc0[nf2];
                const uint32_t* bhp = &kfh[nf2 >> 1][(nf2 & 1) * 2];
                const uint32_t* blp = &kfl[nf2 >> 1][(nf2 & 1) * 2];
                mma_bf16(c, qfh, bhp);
                mma_bf16(c, qfh, blp);
                mma_bf16(c, qfl, bhp);
            }
        }

        // ---- Stage B: S(1) = Q @ K[64:128]^T  interleaved with softmax(0) ----
        uint32_t pf0h[4][4], pf0l[4][4];
#pragma unroll
        for (int ks = 0; ks < 4; ks++) {
            uint32_t qfh[4], qfl[4];
            {
                uint32_t a = sb + AT_QH + (uint32_t)(w * 16 + (lane & 15)) * 144
                           + (ks * 16 + (lane >> 4) * 8) * 2;
                ldsm4(qfh, a);
                ldsm4(qfl, a + AT_TS);
            }
            uint32_t kfh[4][4], kfl[4][4];
#pragma unroll
            for (int g2 = 0; g2 < 4; g2++) {
                uint32_t a = kvb
                    + (uint32_t)(64 + g2 * 16 + (lane & 7) + ((lane >> 4) << 3)) * 144
                    + (ks * 16 + ((lane >> 3) & 1) * 8) * 2;
                ldsm4(kfh[g2], a);
                ldsm4(kfl[g2], a + AT_TS);
            }
#pragma unroll
            for (int nf2 = 0; nf2 < 8; nf2++) {
                float* c = sacc1[nf2];
                const uint32_t* bhp = &kfh[nf2 >> 1][(nf2 & 1) * 2];
                const uint32_t* blp = &kfl[nf2 >> 1][(nf2 & 1) * 2];
                mma_bf16(c, qfh, bhp);
                mma_bf16(c, qfh, blp);
                mma_bf16(c, qfl, bhp);
            }
            // softmax(0) chunk ks: sacc0[2ks], sacc0[2ks+1] -> pf0[ks]
#pragma unroll
            for (int j = 0; j < 2; j++) {
                int nf2 = 2 * ks + j;
                float* c = sacc0[nf2];
                int idx = d0 - nf2 * 8;
                float p0 = ex2f(fmaf(sbias[idx],     LOG2E, c[0]));
                float p1 = ex2f(fmaf(sbias[idx - 1], LOG2E, c[1]));
                float p2 = ex2f(fmaf(sbias[idx + 8], LOG2E, c[2]));
                float p3 = ex2f(fmaf(sbias[idx + 7], LOG2E, c[3]));
                lsumA += p0 + p1;
                lsumB += p2 + p3;
                split2(p0, p1, pf0h[ks][j * 2 + 0], pf0l[ks][j * 2 + 0]);
                split2(p2, p3, pf0h[ks][j * 2 + 1], pf0l[ks][j * 2 + 1]);
            }
        }

        // ---- Stage C: O += P(0) @ V[0:64]  interleaved with softmax(1) ----
        const uint32_t vb = kvb + 2 * AT_TS;
        uint32_t pf1h[4][4], pf1l[4][4];
#pragma unroll
        for (int ks2 = 0; ks2 < 4; ks2++) {
            uint32_t vfh[4][4], vfl[4][4];
#pragma unroll
            for (int dblk = 0; dblk < 4; dblk++) {
                uint32_t a = vb
                    + (uint32_t)(ks2 * 16 + (lane & 7) + ((lane >> 3) & 1) * 8) * 144
                    + (dblk * 16 + ((lane >> 4) << 3)) * 2;
                ldsm4t(vfh[dblk], a);
                ldsm4t(vfl[dblk], a + AT_TS);
            }
#pragma unroll
            for (int dblk = 0; dblk < 4; dblk++)
#pragma unroll
                for (int sub = 0; sub < 2; sub++) {
                    float* o = oacc[dblk * 2 + sub];
                    mma_bf16(o, pf0h[ks2], &vfh[dblk][sub * 2]);
                    mma_bf16(o, pf0h[ks2], &vfl[dblk][sub * 2]);
                    mma_bf16(o, pf0l[ks2], &vfh[dblk][sub * 2]);
                }
            // softmax(1) chunk ks2: sacc1 -> pf1[ks2]
#pragma unroll
            for (int j = 0; j < 2; j++) {
                int nf2 = 2 * ks2 + j;
                float* c = sacc1[nf2];
                int idx = d0 - (8 + nf2) * 8;
                float p0 = ex2f(fmaf(sbias[idx],     LOG2E, c[0]));
                float p1 = ex2f(fmaf(sbias[idx - 1], LOG2E, c[1]));
                float p2 = ex2f(fmaf(sbias[idx + 8], LOG2E, c[2]));
                float p3 = ex2f(fmaf(sbias[idx + 7], LOG2E, c[3]));
                lsumA += p0 + p1;
                lsumB += p2 + p3;
                split2(p0, p1, pf1h[ks2][j * 2 + 0], pf1l[ks2][j * 2 + 0]);
                split2(p2, p3, pf1h[ks2][j * 2 + 1], pf1l[ks2][j * 2 + 1]);
            }
        }

        // ---- Stage D: O += P(1) @ V[64:128] ----
#pragma unroll
        for (int ks2 = 0; ks2 < 4; ks2++) {
            uint32_t vfh[4][4], vfl[4][4];
#pragma unroll
            for (int dblk = 0; dblk < 4; dblk++) {
                uint32_t a = vb
                    + (uint32_t)(64 + ks2 * 16 + (lane & 7) + ((lane >> 3) & 1) * 8) * 144
                    + (dblk * 16 + ((lane >> 4) << 3)) * 2;
                ldsm4t(vfh[dblk], a);
                ldsm4t(vfl[dblk], a + AT_TS);
            }
#pragma unroll
            for (int dblk = 0; dblk < 4; dblk++)
#pragma unroll
                for (int sub = 0; sub < 2; sub++) {
                    float* o = oacc[dblk * 2 + sub];
                    mma_bf16(o, pf1h[ks2], &vfh[dblk][sub * 2]);
                    mma_bf16(o, pf1h[ks2], &vfl[dblk][sub * 2]);
                    mma_bf16(o, pf1l[ks2], &vfh[dblk][sub * 2]);
                }
        }
        __syncthreads();
    }

    // ---- row-sum reduce within quad, epilogue ----
    lsumA += __shfl_xor_sync(0xffffffffu, lsumA, 1);
    lsumA += __shfl_xor_sync(0xffffffffu, lsumA, 2);
    lsumB += __shfl_xor_sync(0xffffffffu, lsumB, 1);
    lsumB += __shfl_xor_sync(0xffffffffu, lsumB, 2);
    const float inv0 = 1.0f / lsumA;
    const float inv1 = 1.0f / lsumB;
    const int row0 = q0 + w * 16 + g;
    const size_t base0 = (size_t)(b * 2048 + row0) * 1024 + h * 64;
    const size_t base1 = (size_t)(b * 2048 + row0 + 8) * 1024 + h * 64;
#pragma unroll
    for (int nfd = 0; nfd < 8; nfd++) {
        int d = nfd * 8 + 2 * tig;
        uint32_t hi, lo;
        split2(oacc[nfd][0] * inv0, oacc[nfd][1] * inv0, hi, lo);
        *(uint32_t*)(g_ch + base0 + d) = hi;
        *(uint32_t*)(g_cl + base0 + d) = lo;
        split2(oacc[nfd][2] * inv1, oacc[nfd][3] * inv1, hi, lo);
        *(uint32_t*)(g_ch + base1 + d) = hi;
        *(uint32_t*)(g_cl + base1 + d) = lo;
    }
}

// ---------------- launch ----------------
extern "C" void kernel_launch(void* const* d_in, const int* in_sizes, int n_in,
                              void* d_out, int out_size)
{
    const float* x  = (const float*)d_in[0];
    const float* Wq = (const float*)d_in[1];
    const float* Wk = (const float*)d_in[2];
    const float* Wv = (const float*)d_in[3];
    const float* Wo = (const float*)d_in[4];
    const float* bo = (const float*)d_in[5];
    const float* bt = (const float*)d_in[6];
    float* out = (float*)d_out;

    cudaFuncSetAttribute(proj_kernel<0>, cudaFuncAttributeMaxDynamicSharedMemorySize, 2 * PST);
    cudaFuncSetAttribute(proj_kernel<1>, cudaFuncAttributeMaxDynamicSharedMemorySize, 2 * PST);
    cudaFuncSetAttribute(attn_kernel,    cudaFuncAttributeMaxDynamicSharedMemorySize, AT_SMEM);

    split_x_kernel<<<2048, 256>>>(x);
    split_w_kernel<<<dim3(256, 4), 256>>>(Wq, Wk, Wv, Wo);

    proj_kernel<0><<<dim3(64, 8, 3), 256, 2 * PST>>>(nullptr, nullptr);

    attn_kernel<<<dim3(16, 64), 256, AT_SMEM>>>(bt);

    proj_kernel<1><<<dim3(64, 8), 256, 2 * PST>>>(bo, out);
}